// round 13
// baseline (speedup 1.0000x reference)
#include <cuda_runtime.h>
#include <cuda_bf16.h>
#include <cstdint>

// Conv1dLocal via mma.sync bf16 split-precision (sm_100 safe: no tcgen05).
// out[b,o,s] = sum_{i,k} x[b,i,s+k]*w[o,i,s,k]; per-s GEMM M=64(o) N=32(b) K=448.
// CTA = 4 s (1 warp per s-GEMM), grid 128. K streamed as 8 i-chunks of 8
// (kk = 8*i_loc + k, slot7 = 0 pad -> K'=64, 4 ksteps of m16n8k16).
// Split precision: w=wh+wl, x=xh+xl; D = wh*xh + wl*xh + wh*xl (drop ll).
// Staging: cp.async dense (w runs 112B 16B-aligned thanks to s-tiling; x 5x8B),
// cooperative cvt to XOR-swizzled bf16 tiles, ldmatrix + mma.sync mainloop.

#define B_    32
#define IC_   64
#define OC_   64
#define S_    512
#define KW_   7
#define L_    518

#define STILE     4
#define NCHUNK    8
#define ICHUNK    8
#define THREADS   128

// smem offsets (bytes)
#define SM_A      0                     // A tiles: [term][s][64 x 128B]
#define A_TILE    (64 * 128)            // 8192
#define SM_A_LO   (4 * A_TILE)          // 32768
#define SM_B      (8 * A_TILE)          // 65536 : B tiles [term][s][32 x 128B]
#define B_TILE    (32 * 128)            // 4096
#define SM_B_LO   (SM_B + 4 * B_TILE)   // 81920
#define SM_RAWW   (SM_B + 8 * B_TILE)   // 98304 : 512 runs x 112B
#define SM_RAWX   (SM_RAWW + 512 * 112) // 155648 : 256 runs x 48B
#define SMEM_TOTAL (SM_RAWX + 256 * 48) // 167936

__device__ __forceinline__ void cp16(unsigned dst, const void* src) {
    asm volatile("cp.async.cg.shared.global [%0], [%1], 16;" :: "r"(dst), "l"(src));
}
__device__ __forceinline__ void cp8(unsigned dst, const void* src) {
    asm volatile("cp.async.ca.shared.global [%0], [%1], 8;" :: "r"(dst), "l"(src));
}
__device__ __forceinline__ void ldsm4(unsigned addr, unsigned &r0, unsigned &r1,
                                      unsigned &r2, unsigned &r3) {
    asm volatile("ldmatrix.sync.aligned.m8n8.x4.shared.b16 {%0,%1,%2,%3}, [%4];"
                 : "=r"(r0), "=r"(r1), "=r"(r2), "=r"(r3) : "r"(addr));
}
__device__ __forceinline__ void mma16816(float* c, unsigned a0, unsigned a1,
                                         unsigned a2, unsigned a3,
                                         unsigned b0, unsigned b1) {
    asm volatile(
        "mma.sync.aligned.m16n8k16.row.col.f32.bf16.bf16.f32 "
        "{%0,%1,%2,%3}, {%4,%5,%6,%7}, {%8,%9}, {%0,%1,%2,%3};"
        : "+f"(c[0]), "+f"(c[1]), "+f"(c[2]), "+f"(c[3])
        : "r"(a0), "r"(a1), "r"(a2), "r"(a3), "r"(b0), "r"(b1));
}

__global__ __launch_bounds__(THREADS, 1)
void conv1d_local_mma(const float* __restrict__ x,
                      const float* __restrict__ w,
                      float* __restrict__ out)
{
    extern __shared__ char smem[];
    const unsigned smem_u = (unsigned)__cvta_generic_to_shared(smem);
    const int tid  = threadIdx.x;
    const int lane = tid & 31;
    const int warp = tid >> 5;
    const int s0   = blockIdx.x * STILE;

    float* rawW = reinterpret_cast<float*>(smem + SM_RAWW);
    float* rawX = reinterpret_cast<float*>(smem + SM_RAWX);

    // ---- stage(c): issue cp.async for chunk c's raw data
    auto stage = [&](int c) {
        // w: 512 runs (o,i_loc), 112B dense each, 7 x cp16; 4 runs/thread
        #pragma unroll
        for (int m = 0; m < 4; ++m) {
            int r = tid + 128 * m;
            int o = r >> 3, il = r & 7;
            int i = c * ICHUNK + il;
            const float* src = w + (((size_t)(o * IC_ + i) * S_ + s0) * KW_);
            unsigned dst = smem_u + SM_RAWW + r * 112;
            #pragma unroll
            for (int p = 0; p < 7; ++p)
                cp16(dst + p * 16, src + p * 4);
        }
        // x: 256 runs (b,i_loc), 10 floats = 5 x cp8; 2 runs/thread
        #pragma unroll
        for (int m = 0; m < 2; ++m) {
            int r = tid + 128 * m;
            int b = r >> 3, il = r & 7;
            int i = c * ICHUNK + il;
            const float* src = x + ((size_t)(b * IC_ + i) * L_ + s0);
            unsigned dst = smem_u + SM_RAWX + r * 48;
            #pragma unroll
            for (int p = 0; p < 5; ++p)
                cp8(dst + p * 8, src + p * 2);
        }
        asm volatile("cp.async.commit_group;");
    };

    stage(0);

    // accumulators: acc[mt][nt][4]
    float acc[4][4][4];
    #pragma unroll
    for (int a = 0; a < 4; ++a)
        #pragma unroll
        for (int b = 0; b < 4; ++b)
            #pragma unroll
            for (int q = 0; q < 4; ++q) acc[a][b][q] = 0.f;

    // per-warp tile bases for the mma phase
    const unsigned Ah = smem_u + SM_A    + warp * A_TILE;
    const unsigned Al = smem_u + SM_A_LO + warp * A_TILE;
    const unsigned Bh = smem_u + SM_B    + warp * B_TILE;
    const unsigned Bl = smem_u + SM_B_LO + warp * B_TILE;

    #pragma unroll 1
    for (int c = 0; c < NCHUNK; ++c) {
        asm volatile("cp.async.wait_group 0;");
        __syncthreads();   // raw(c) visible; all warps done with tiles(c-1)

        // ---- convert w raw -> A hi/lo tiles. 2048 tasks (run, s); 16/thread
        #pragma unroll 4
        for (int j = 0; j < 16; ++j) {
            int t  = tid + 128 * j;
            int sl = t & 3;
            int r  = t >> 2;            // 0..511
            int o  = r >> 3, il = r & 7;
            const float* v = rawW + r * 28 + sl * 7;
            unsigned short uh[8], ul[8];
            #pragma unroll
            for (int k = 0; k < 7; ++k) {
                float f = v[k];
                __nv_bfloat16 h = __float2bfloat16(f);
                __nv_bfloat16 l = __float2bfloat16(f - __bfloat162float(h));
                uh[k] = __bfloat16_as_ushort(h);
                ul[k] = __bfloat16_as_ushort(l);
            }
            uh[7] = 0; ul[7] = 0;
            unsigned off = (unsigned)(sl * A_TILE + o * 128 + ((il ^ (o & 7)) << 4));
            char* ph = smem + SM_A    + off;
            char* pl = smem + SM_A_LO + off;
            #pragma unroll
            for (int n = 0; n < 4; ++n) {
                int j2 = (tid + n) & 3;   // bank stagger
                unsigned wh2 = (unsigned)uh[2*j2] | ((unsigned)uh[2*j2+1] << 16);
                unsigned wl2 = (unsigned)ul[2*j2] | ((unsigned)ul[2*j2+1] << 16);
                *reinterpret_cast<unsigned*>(ph + 4*j2) = wh2;
                *reinterpret_cast<unsigned*>(pl + 4*j2) = wl2;
            }
        }
        // ---- convert x raw -> B hi/lo tiles. 1024 tasks; 8/thread
        #pragma unroll 4
        for (int j = 0; j < 8; ++j) {
            int t  = tid + 128 * j;
            int sl = t & 3;
            int r  = t >> 2;            // 0..255
            int b  = r >> 3, il = r & 7;
            const float* v = rawX + r * 12 + sl;
            unsigned short uh[8], ul[8];
            #pragma unroll
            for (int k = 0; k < 7; ++k) {
                float f = v[k];
                __nv_bfloat16 h = __float2bfloat16(f);
                __nv_bfloat16 l = __float2bfloat16(f - __bfloat162float(h));
                uh[k] = __bfloat16_as_ushort(h);
                ul[k] = __bfloat16_as_ushort(l);
            }
            uh[7] = 0; ul[7] = 0;
            unsigned off = (unsigned)(sl * B_TILE + b * 128 + ((il ^ (b & 7)) << 4));
            char* ph = smem + SM_B    + off;
            char* pl = smem + SM_B_LO + off;
            #pragma unroll
            for (int n = 0; n < 4; ++n) {
                int j2 = (tid + n) & 3;
                unsigned wh2 = (unsigned)uh[2*j2] | ((unsigned)uh[2*j2+1] << 16);
                unsigned wl2 = (unsigned)ul[2*j2] | ((unsigned)ul[2*j2+1] << 16);
                *reinterpret_cast<unsigned*>(ph + 4*j2) = wh2;
                *reinterpret_cast<unsigned*>(pl + 4*j2) = wl2;
            }
        }
        __syncthreads();   // tiles(c) ready; raw fully consumed

        if (c + 1 < NCHUNK) stage(c + 1);   // overlaps with mma below

        // ---- mma phase: this warp's s-GEMM, K'=64 -> 4 ksteps
        #pragma unroll
        for (int ks = 0; ks < 4; ++ks) {
            // B fragments: row n, chunk 2ks + ((lane>>3)&1), nt2 in {0,1}
            unsigned bh[8], bl[8];
            #pragma unroll
            for (int nt2 = 0; nt2 < 2; ++nt2) {
                int row = nt2 * 16 + ((lane >> 4) << 3) + (lane & 7);
                int ch  = 2 * ks + ((lane >> 3) & 1);
                unsigned byte = (unsigned)(row * 128 + ((ch ^ (row & 7)) << 4));
                ldsm4(Bh + byte, bh[nt2*4+0], bh[nt2*4+1], bh[nt2*4+2], bh[nt2*4+3]);
                ldsm4(Bl + byte, bl[nt2*4+0], bl[nt2*4+1], bl[nt2*4+2], bl[nt2*4+3]);
            }
            #pragma unroll
            for (int mt = 0; mt < 4; ++mt) {
                int row = mt * 16 + (lane & 15);
                int ch  = 2 * ks + (lane >> 4);
                unsigned byte = (unsigned)(row * 128 + ((ch ^ (row & 7)) << 4));
                unsigned a0, a1, a2, a3, c0, c1, c2, c3;
                ldsm4(Ah + byte, a0, a1, a2, a3);
                ldsm4(Al + byte, c0, c1, c2, c3);
                #pragma unroll
                for (int nt = 0; nt < 4; ++nt) {
                    unsigned b0 = bh[nt*2], b1 = bh[nt*2+1];
                    unsigned e0 = bl[nt*2], e1 = bl[nt*2+1];
                    mma16816(acc[mt][nt], a0, a1, a2, a3, b0, b1); // wh*xh
                    mma16816(acc[mt][nt], c0, c1, c2, c3, b0, b1); // wl*xh
                    mma16816(acc[mt][nt], a0, a1, a2, a3, e0, e1); // wh*xl
                }
            }
        }
    }

    // ---- epilogue: direct STG, full coverage
    const int s_g = s0 + warp;
    #pragma unroll
    for (int mt = 0; mt < 4; ++mt) {
        #pragma unroll
        for (int nt = 0; nt < 4; ++nt) {
            int row0 = mt * 16 + (lane >> 2);
            int col0 = nt * 8 + (lane & 3) * 2;
            out[(size_t)(col0    ) * (OC_ * S_) + (size_t)(row0    ) * S_ + s_g] = acc[mt][nt][0];
            out[(size_t)(col0 + 1) * (OC_ * S_) + (size_t)(row0    ) * S_ + s_g] = acc[mt][nt][1];
            out[(size_t)(col0    ) * (OC_ * S_) + (size_t)(row0 + 8) * S_ + s_g] = acc[mt][nt][2];
            out[(size_t)(col0 + 1) * (OC_ * S_) + (size_t)(row0 + 8) * S_ + s_g] = acc[mt][nt][3];
        }
    }
}

extern "C" void kernel_launch(void* const* d_in, const int* in_sizes, int n_in,
                              void* d_out, int out_size)
{
    const float* x = (const float*)d_in[0];
    const float* w = (const float*)d_in[1];
    float* out = (float*)d_out;

    cudaFuncSetAttribute(conv1d_local_mma,
                         cudaFuncAttributeMaxDynamicSharedMemorySize, SMEM_TOTAL);

    conv1d_local_mma<<<S_ / STILE, THREADS, SMEM_TOTAL>>>(x, w, out);
}